// round 17
// baseline (speedup 1.0000x reference)
#include <cuda_runtime.h>
#include <cuda_fp16.h>
#include <cstdint>

#define K_DIM 4096
#define N_DIM 4096
#define M_DIM 8192

#define BM 128
#define BN 256
#define BK 32
#define NTILES (K_DIM / BK)
#define THREADS 512

#define ROWB 80                       // 32 halves (64B) + 16B pad
#define A_STAGE (BM * ROWB)           // 10240
#define B_STAGE (BN * ROWB)           // 20480
#define A_SM2 (2 * A_STAGE)           // 20480
#define SMEM_TOTAL (A_SM2 + 2 * B_STAGE)  // 61440

#define CONV_BLOCKS 16384
#define DEQ_BLOCKS 512

// Dequantized weights [N][K], K contiguous, k PERMUTED within 8-blocks
// (order 0,4,1,5,2,6,3,7). g_X uses the same permutation -> dot products equal.
__device__ __half g_W[(size_t)N_DIM * K_DIM];
__device__ __half g_X[(size_t)M_DIM * K_DIM];

// ---------------- Kernel 0+1 merged: prep (convert x || dequant W) ----------------
__global__ __launch_bounds__(256) void prep_kernel(const float* __restrict__ xf,
                                                   const int* __restrict__ qw,
                                                   const float* __restrict__ scales,
                                                   const int* __restrict__ qz) {
    if (blockIdx.x < CONV_BLOCKS) {
        size_t i = ((size_t)blockIdx.x * blockDim.x + threadIdx.x) * 8;
        float4 v0 = *reinterpret_cast<const float4*>(xf + i);
        float4 v1 = *reinterpret_cast<const float4*>(xf + i + 4);
        __half h[8];
        // permuted order: x0,x4,x1,x5,x2,x6,x3,x7
        h[0] = __float2half_rn(v0.x); h[1] = __float2half_rn(v1.x);
        h[2] = __float2half_rn(v0.y); h[3] = __float2half_rn(v1.y);
        h[4] = __float2half_rn(v0.z); h[5] = __float2half_rn(v1.z);
        h[6] = __float2half_rn(v0.w); h[7] = __float2half_rn(v1.w);
        *reinterpret_cast<uint4*>(&g_X[i]) = *reinterpret_cast<const uint4*>(h);
    } else {
        // warp owns 32 consecutive n, one group g (16 qweight rows). LOP3 magic:
        // t = ((w>>4j)&0x000F000F)|0x64006400 -> half2(1024+v_j, 1024+v_{j+4});
        // hsub2 of (1024+z) exact; hmul2 by fp16 scale = reference rounding.
        int gw = (blockIdx.x - CONV_BLOCKS) * 8 + (threadIdx.x >> 5);  // 0..4095
        int lane = threadIdx.x & 31;
        int n = (gw & 127) * 32 + lane;
        int g = gw >> 7;                                // 0..31
        __half s = __float2half_rn(scales[g * N_DIM + n]);
        __half2 s2 = __half2half2(s);
        int z = ((qz[g * (N_DIM / 8) + (n >> 3)] >> ((n & 7) * 4)) & 0xF) + 1;
        __half2 mz = __half2half2(__float2half_rn(1024.0f + (float)z));
        const int r0 = g * 16;
#pragma unroll
        for (int i = 0; i < 16; i++) {
            int w = qw[(size_t)(r0 + i) * N_DIM + n];
            uint32_t outv[4];
#pragma unroll
            for (int j = 0; j < 4; j++) {
                uint32_t t = (((uint32_t)w >> (4 * j)) & 0x000F000Fu) | 0x64006400u;
                __half2 hv = __hmul2(__hsub2(*reinterpret_cast<__half2*>(&t), mz), s2);
                outv[j] = *reinterpret_cast<uint32_t*>(&hv);
            }
            *reinterpret_cast<uint4*>(&g_W[(size_t)n * K_DIM + (r0 + i) * 8]) =
                *reinterpret_cast<const uint4*>(outv);
        }
    }
}

// ---------------- Kernel 2: GEMM 128x256x32, 512 threads ----------------
// 16 warps = 2(M) x 8(N), warp tile 64x32 (identical per-thread load to R15:
// 122 regs, fits 128-reg cap at 512 threads). 1 CTA/SM, 16 warps/SM.
// L2 ingress per chunk: 24KB (vs 64KB/SM at the 128x128 2-CTA config).
__global__ __launch_bounds__(THREADS) void gemm_kernel(const float* __restrict__ biasf,
                                                       float* __restrict__ out) {
    extern __shared__ __align__(128) char smem[];
    const uint32_t sbase = (uint32_t)__cvta_generic_to_shared(smem);
    const int tid = threadIdx.x;
    const int lane = tid & 31;
    const int warp = tid >> 5;
    const int warpM = warp & 1;   // 0..1
    const int warpN = warp >> 1;  // 0..7
    const int bm = blockIdx.y * BM;
    const int bn = blockIdx.x * BN;

    float c[4][4][4];
#pragma unroll
    for (int i = 0; i < 4; i++)
#pragma unroll
        for (int j = 0; j < 4; j++)
#pragma unroll
            for (int e = 0; e < 4; e++) c[i][j][e] = 0.0f;

    auto load_stage = [&](int s, int kt) {
        // A: 512 vectors, one per thread
        {
            int row = tid >> 2;          // 0..127
            int v = tid & 3;
            const __half* srcA = g_X + (size_t)(bm + row) * K_DIM + kt * BK + v * 8;
            uint32_t dA = sbase + s * A_STAGE + row * ROWB + v * 16;
            asm volatile("cp.async.cg.shared.global [%0], [%1], 16;" :: "r"(dA), "l"(srcA));
        }
        // B: 1024 vectors, two per thread
#pragma unroll
        for (int i = 0; i < 2; i++) {
            int id = tid + i * THREADS;  // 0..1023
            int row = id >> 2;           // 0..255
            int v = id & 3;
            const __half* srcB = g_W + (size_t)(bn + row) * K_DIM + kt * BK + v * 8;
            uint32_t dB = sbase + A_SM2 + s * B_STAGE + row * ROWB + v * 16;
            asm volatile("cp.async.cg.shared.global [%0], [%1], 16;" :: "r"(dB), "l"(srcB));
        }
        asm volatile("cp.async.commit_group;");
    };

    load_stage(0, 0);
    int cur = 0;

    for (int kt = 0; kt < NTILES; kt++) {
        asm volatile("cp.async.wait_group 0;");
        __syncthreads();
        if (kt + 1 < NTILES) load_stage(cur ^ 1, kt + 1);

        uint32_t abase = sbase + cur * A_STAGE;
        uint32_t bbase = sbase + A_SM2 + cur * B_STAGE;
#pragma unroll
        for (int kk = 0; kk < BK; kk += 16) {
            uint32_t a[4][4];
#pragma unroll
            for (int fm = 0; fm < 4; fm++) {
                int m0 = warpM * 64 + fm * 16 + (lane & 15);
                uint32_t addr = abase + m0 * ROWB + (kk + ((lane >> 4) << 3)) * 2;
                asm volatile("ldmatrix.sync.aligned.m8n8.x4.shared.b16 {%0,%1,%2,%3}, [%4];"
                             : "=r"(a[fm][0]), "=r"(a[fm][1]), "=r"(a[fm][2]), "=r"(a[fm][3])
                             : "r"(addr));
            }
            uint32_t b[4][2];
#pragma unroll
            for (int fn = 0; fn < 4; fn++) {
                int n0 = warpN * 32 + fn * 8 + (lane & 7);
                uint32_t addr = bbase + n0 * ROWB + (kk + ((lane >> 3) & 1) * 8) * 2;
                asm volatile("ldmatrix.sync.aligned.m8n8.x2.shared.b16 {%0,%1}, [%2];"
                             : "=r"(b[fn][0]), "=r"(b[fn][1])
                             : "r"(addr));
            }
#pragma unroll
            for (int fm = 0; fm < 4; fm++)
#pragma unroll
                for (int fn = 0; fn < 4; fn++) {
                    asm volatile(
                        "mma.sync.aligned.m16n8k16.row.col.f32.f16.f16.f32 "
                        "{%0,%1,%2,%3}, {%4,%5,%6,%7}, {%8,%9}, {%0,%1,%2,%3};"
                        : "+f"(c[fm][fn][0]), "+f"(c[fm][fn][1]),
                          "+f"(c[fm][fn][2]), "+f"(c[fm][fn][3])
                        : "r"(a[fm][0]), "r"(a[fm][1]), "r"(a[fm][2]), "r"(a[fm][3]),
                          "r"(b[fn][0]), "r"(b[fn][1]));
                }
        }
        cur ^= 1;
    }

    // Epilogue: fp16(sum) + fp16(bias) in fp16, store f32 (reference rounding).
    const int row_in = lane >> 2;         // 0..7
    const int col_in = (lane & 3) * 2;    // 0,2,4,6
#pragma unroll
    for (int fn = 0; fn < 4; fn++) {
        int n = bn + warpN * 32 + fn * 8 + col_in;
        __half bh0 = __float2half_rn(biasf[n]);
        __half bh1 = __float2half_rn(biasf[n + 1]);
#pragma unroll
        for (int fm = 0; fm < 4; fm++) {
            int m = bm + warpM * 64 + fm * 16 + row_in;
            float2 v0, v1;
            v0.x = __half2float(__hadd(__float2half_rn(c[fm][fn][0]), bh0));
            v0.y = __half2float(__hadd(__float2half_rn(c[fm][fn][1]), bh1));
            v1.x = __half2float(__hadd(__float2half_rn(c[fm][fn][2]), bh0));
            v1.y = __half2float(__hadd(__float2half_rn(c[fm][fn][3]), bh1));
            *reinterpret_cast<float2*>(&out[(size_t)m * N_DIM + n]) = v0;
            *reinterpret_cast<float2*>(&out[(size_t)(m + 8) * N_DIM + n]) = v1;
        }
    }
}

extern "C" void kernel_launch(void* const* d_in, const int* in_sizes, int n_in,
                              void* d_out, int out_size) {
    const float* x       = (const float*)d_in[0];
    const int*   qweight = (const int*)d_in[1];
    const float* scales  = (const float*)d_in[2];
    const int*   qzeros  = (const int*)d_in[3];
    // d_in[4] = g_idx: k/128, folded into dequant indexing
    const float* bias    = (const float*)d_in[5];
    float* out = (float*)d_out;

    prep_kernel<<<CONV_BLOCKS + DEQ_BLOCKS, 256>>>(x, qweight, scales, qzeros);

    cudaFuncSetAttribute(gemm_kernel, cudaFuncAttributeMaxDynamicSharedMemorySize, SMEM_TOTAL);
    dim3 grid(N_DIM / BN, M_DIM / BM);
    gemm_kernel<<<grid, THREADS, SMEM_TOTAL>>>(bias, out);
}